// round 10
// baseline (speedup 1.0000x reference)
#include <cuda_runtime.h>

#define NPTS   8192
#define TPB    256
#define NC     10
#define NCELL  100
#define CAP    192       // per-cell capacity (mean 82; Poisson tail @192 ~ 0)
#define PADOWN (CAP + 8) // own tile padded for 4-wide self-pair access
#define NPB    200       // blocks: 100 cells x 2 halves; also binning slices
#define PPB    41        // ceil(8192/200) points binned per block
#define MIN_DISTF 0.1f

// scratch (module-load zero-init; last block resets all counters each launch)
__device__ int   g_n[NCELL];
__device__ float g_binx[NCELL * CAP];
__device__ float g_biny[NCELL * CAP];
__device__ float g_msep[NPB];
__device__ float g_pen[NPB];
__device__ int   g_sync = 0;   // phase barrier
__device__ int   g_cnt  = 0;   // completion ticket

__device__ __forceinline__ float rsq(float x) {
    float r;
    asm("rsqrt.approx.f32 %0, %1;" : "=f"(r) : "f"(x));
    return r;
}

__device__ __forceinline__ int cell_of(float x, float y) {
    int cx = (int)(x * 10.f); cx = cx > 9 ? 9 : cx;
    int cy = (int)(y * 10.f); cy = cy > 9 ? 9 : cy;
    return cy * NC + cx;
}

// branchless pair: d2<=0 or d>=0.1 (incl. 1e9 sentinels) contribute exactly 0
#define PAIR(xi, yi, xj, yj, acc)                          \
    {                                                      \
        float dx_ = (xi) - (xj), dy_ = (yi) - (yj);        \
        float d2_ = fmaf(dx_, dx_, dy_ * dy_);             \
        float r_  = rsq(d2_);                              \
        float m_  = fmaxf(fmaf(d2_, -r_, MIN_DISTF), 0.f); \
        (acc) = fmaf(m_, m_, (acc));                       \
    }

__global__ void __launch_bounds__(TPB) k_all(const float2* __restrict__ pts,
                                             const float2* __restrict__ tg,
                                             float* __restrict__ out) {
    __shared__ __align__(16) float sh_ox[PADOWN];
    __shared__ __align__(16) float sh_oy[PADOWN];
    __shared__ __align__(16) float sh_nx[4 * CAP];
    __shared__ __align__(16) float sh_ny[4 * CAP];
    __shared__ float sm[TPB / 32];
    __shared__ int   lastFlag;

    const int tid = threadIdx.x;
    const int bid = blockIdx.x;
    const int lane = tid & 31, w = tid >> 5;

    // ================= Phase A: bin slice + MSE partial =================
    float v = 0.f;
    if (tid < PPB) {
        int i = bid * PPB + tid;
        if (i < NPTS) {
            float2 p = pts[i];
            int c    = cell_of(p.x, p.y);
            int slot = atomicAdd(&g_n[c], 1);
            if (slot < CAP) {
                g_binx[c * CAP + slot] = p.x;
                g_biny[c * CAP + slot] = p.y;
            }
            float2 t = tg[i];
            float dx = p.x - t.x, dy = p.y - t.y;
            v = fmaf(dx, dx, dy * dy);
        }
    }
#pragma unroll
    for (int o = 16; o > 0; o >>= 1) v += __shfl_xor_sync(0xffffffffu, v, o);
    if (lane == 0) sm[w] = v;
    __syncthreads();
    if (tid == 0) {
        float s = 0.f;
#pragma unroll
        for (int x = 0; x < TPB / 32; x++) s += sm[x];
        g_msep[bid] = s;
        __threadfence();
        atomicAdd(&g_sync, 1);
        int got;
        do {
            asm volatile("ld.acquire.gpu.global.b32 %0, [%1];"
                         : "=r"(got) : "l"(&g_sync));
            if (got < NPB) __nanosleep(32);
        } while (got < NPB);
    }
    __syncthreads();   // releases the block; acquire-load ordered the bin data

    // ================= Phase B: per-(cell, half) pairs =================
    const int c  = bid % NCELL;
    const int h  = bid / NCELL;
    const int cx = c % NC, cy = c / NC;

    // neighbor cell list (half shell); all count loads issued independently
    int nbc[4]; int nnb = 0;
    if (cx + 1 < NC) nbc[nnb++] = c + 1;
    if (cy + 1 < NC) {
        if (cx > 0)      nbc[nnb++] = c + NC - 1;
        nbc[nnb++] = c + NC;
        if (cx + 1 < NC) nbc[nnb++] = c + NC + 1;
    }
    int cnts[4];
    int n0 = g_n[c];
#pragma unroll
    for (int k = 0; k < 4; k++) cnts[k] = (k < nnb) ? g_n[nbc[k]] : 0;

    n0 = n0 > CAP ? CAP : n0;
    const int n0r = (n0 + 3) & ~3;
    // fill own tile; pad [n0, n0r+4) with far sentinels for 4-wide self loop
    for (int k = tid; k < n0r + 4; k += TPB) {
        bool real = k < n0;
        sh_ox[k] = real ? g_binx[c * CAP + k] : 1e9f;
        sh_oy[k] = real ? g_biny[c * CAP + k] : 1e9f;
    }

    int nn = 0;
    for (int k = 0; k < nnb; k++) {
        int cc  = nbc[k];
        int cnt = cnts[k];
        cnt = cnt > CAP ? CAP : cnt;
        for (int t = tid; t < cnt; t += TPB) {
            sh_nx[nn + t] = g_binx[cc * CAP + t];
            sh_ny[nn + t] = g_biny[cc * CAP + t];
        }
        nn += cnt;
    }
    __syncthreads();

    const float4* ox4 = reinterpret_cast<const float4*>(sh_ox);
    const float4* oy4 = reinterpret_cast<const float4*>(sh_oy);
    const int     ni4 = n0r >> 2;

    float a0 = 0.f, a1 = 0.f, a2 = 0.f, a3 = 0.f;

    // cross-cell: this half's candidates j vs all own points (4 indep chains)
    for (int j = h * TPB + tid; j < nn; j += 2 * TPB) {
        float xj = sh_nx[j], yj = sh_ny[j];
#pragma unroll 2
        for (int i4 = 0; i4 < ni4; i4++) {
            float4 qx = ox4[i4];
            float4 qy = oy4[i4];
            PAIR(qx.x, qy.x, xj, yj, a0);
            PAIR(qx.y, qy.y, xj, yj, a1);
            PAIR(qx.z, qy.z, xj, yj, a2);
            PAIR(qx.w, qy.w, xj, yj, a3);
        }
    }

    // self-cell pairs on h==1 (that half has less cross work): slot order i<j,
    // 4-wide over the sentinel-padded tail -> 4 independent accumulator chains
    if (h == 1) {
        if (tid < n0) {
            const int   i  = tid;
            const float xi = sh_ox[i], yi = sh_oy[i];
            for (int j = i + 1; j < n0r; j += 4) {
                PAIR(xi, yi, sh_ox[j + 0], sh_oy[j + 0], a0);
                PAIR(xi, yi, sh_ox[j + 1], sh_oy[j + 1], a1);
                PAIR(xi, yi, sh_ox[j + 2], sh_oy[j + 2], a2);
                PAIR(xi, yi, sh_ox[j + 3], sh_oy[j + 3], a3);
            }
        }
    }

    // block reduction
    float pen = (a0 + a1) + (a2 + a3);
#pragma unroll
    for (int o = 16; o > 0; o >>= 1) pen += __shfl_xor_sync(0xffffffffu, pen, o);
    if (lane == 0) sm[w] = pen;
    __syncthreads();
    if (tid == 0) {
        float ps = 0.f;
#pragma unroll
        for (int x = 0; x < TPB / 32; x++) ps += sm[x];
        g_pen[bid] = ps;
        __threadfence();
        int ticket = atomicAdd(&g_cnt, 1);
        lastFlag = (ticket == NPB - 1);
    }
    __syncthreads();

    // ================= Phase C: last block finalizes + resets =================
    if (lastFlag) {
        if (tid < NCELL) g_n[tid] = 0;         // everyone already read g_n
        if (w == 0) {
            double pd = 0.0, md = 0.0;
#pragma unroll
            for (int x = 0; x < NPB / 32 + 1; x++) {
                int idx = lane + x * 32;
                if (idx < NPB) {
                    pd += (double)__ldcg(&g_pen[idx]);
                    md += (double)__ldcg(&g_msep[idx]);
                }
            }
#pragma unroll
            for (int o = 16; o > 0; o >>= 1) {
                pd += __shfl_xor_sync(0xffffffffu, pd, o);
                md += __shfl_xor_sync(0xffffffffu, md, o);
            }
            if (lane == 0) {
                out[0]  = (float)(md * (1.0 / (double)(NPTS * 2)) + pd);
                g_sync  = 0;
                g_cnt   = 0;
            }
        }
    }
}

extern "C" void kernel_launch(void* const* d_in, const int* in_sizes, int n_in,
                              void* d_out, int out_size) {
    const float2* pred = (const float2*)d_in[0];
    const float2* targ = (const float2*)d_in[1];
    k_all<<<NPB, TPB>>>(pred, targ, (float*)d_out);
}

// round 11
// speedup vs baseline: 1.0019x; 1.0019x over previous
#include <cuda_runtime.h>

#define NPTS  8192
#define TPB   512
#define NC    10
#define NCELL 100
#define CAP   192          // own-cell capacity (mean 82; Poisson tail @192 ~ 0)
#define NOWN  (CAP + 8)    // padded for 4-wide self-pair access
#define NSH   (4 * CAP)    // shell capacity (mean ~330)
#define MIN_DISTF 0.1f

// scratch (module-load zero-init; last block resets g_cnt each launch)
__device__ float g_pen[NCELL];
__device__ float g_mse[NCELL];
__device__ int   g_cnt = 0;

__device__ __forceinline__ float rsq(float x) {
    float r;
    asm("rsqrt.approx.f32 %0, %1;" : "=f"(r) : "f"(x));
    return r;
}

// branchless pair: d2<=0 or d>=0.1 (incl. 1e9 sentinels) contribute exactly 0
#define PAIR(xi, yi, xj, yj, acc)                          \
    {                                                      \
        float dx_ = (xi) - (xj), dy_ = (yi) - (yj);        \
        float d2_ = fmaf(dx_, dx_, dy_ * dy_);             \
        float r_  = rsq(d2_);                              \
        float m_  = fmaxf(fmaf(d2_, -r_, MIN_DISTF), 0.f); \
        (acc) = fmaf(m_, m_, (acc));                       \
    }

__global__ void __launch_bounds__(TPB) k_all(const float2* __restrict__ pts,
                                             const float2* __restrict__ tg,
                                             float* __restrict__ out) {
    __shared__ __align__(16) float sOx[NOWN];
    __shared__ __align__(16) float sOy[NOWN];
    __shared__ __align__(16) float sNx[NSH];
    __shared__ __align__(16) float sNy[NSH];
    __shared__ int   cntO, cntN;
    __shared__ float smP[TPB / 32];
    __shared__ float smM[TPB / 32];
    __shared__ int   lastFlag;

    const int tid  = threadIdx.x;
    const int b    = blockIdx.x;
    const int cx   = b % NC, cy = b / NC;
    const int lane = tid & 31, w = tid >> 5;

    if (tid == 0) { cntO = 0; cntN = 0; }
    __syncthreads();

    // ---- scan ALL points (input sits in L2); compact own cell + half shell ----
    for (int k = tid; k < NPTS; k += TPB) {
        float2 q  = pts[k];
        int qcx = (int)(q.x * 10.f); qcx = qcx > 9 ? 9 : qcx;
        int qcy = (int)(q.y * 10.f); qcy = qcy > 9 ? 9 : qcy;
        int dx = qcx - cx, dy = qcy - cy;
        bool own   = (dx | dy) == 0;
        // half shell: (+1,0), (-1,+1), (0,+1), (+1,+1)  (antisymmetric set)
        bool shell = (dy == 0 && dx == 1) || (dy == 1 && (unsigned)(dx + 1) <= 2u);
        if (own) {
            int s = atomicAdd(&cntO, 1);
            if (s < CAP) { sOx[s] = q.x; sOy[s] = q.y; }
        } else if (shell) {
            int s = atomicAdd(&cntN, 1);
            if (s < NSH) { sNx[s] = q.x; sNy[s] = q.y; }
        }
    }

    // ---- MSE slice: 82 points per block (100*82 >= 8192, guarded) ----
    float mse = 0.f;
    if (tid < 82) {
        int i = b * 82 + tid;
        if (i < NPTS) {
            float2 p = pts[i];
            float2 t = tg[i];
            float dx = p.x - t.x, dy = p.y - t.y;
            mse = fmaf(dx, dx, dy * dy);
        }
    }
    __syncthreads();

    const int nO  = cntO > CAP ? CAP : cntO;
    const int nN  = cntN > NSH ? NSH : cntN;
    const int nor = (nO + 3) & ~3;
    // pad own tile tail with far sentinels for the 4-wide loops
    for (int k = nO + tid; k < nor + 4; k += TPB) { sOx[k] = 1e9f; sOy[k] = 1e9f; }
    __syncthreads();

    const float4* ox4 = reinterpret_cast<const float4*>(sOx);
    const float4* oy4 = reinterpret_cast<const float4*>(sOy);
    const int     ni4 = nor >> 2;

    float a0 = 0.f, a1 = 0.f, a2 = 0.f, a3 = 0.f;

    // cross pairs: each thread takes shell candidates strided, 4 indep chains over own
    for (int j = tid; j < nN; j += TPB) {
        float xj = sNx[j], yj = sNy[j];
        for (int i4 = 0; i4 < ni4; i4++) {
            float4 qx = ox4[i4];
            float4 qy = oy4[i4];
            PAIR(qx.x, qy.x, xj, yj, a0);
            PAIR(qx.y, qy.y, xj, yj, a1);
            PAIR(qx.z, qy.z, xj, yj, a2);
            PAIR(qx.w, qy.w, xj, yj, a3);
        }
    }

    // self pairs: slot order i<j, 4-wide over sentinel-padded tail
    if (tid < nO) {
        const float xi = sOx[tid], yi = sOy[tid];
        for (int j = tid + 1; j < nor; j += 4) {
            PAIR(xi, yi, sOx[j + 0], sOy[j + 0], a0);
            PAIR(xi, yi, sOx[j + 1], sOy[j + 1], a1);
            PAIR(xi, yi, sOx[j + 2], sOy[j + 2], a2);
            PAIR(xi, yi, sOx[j + 3], sOy[j + 3], a3);
        }
    }

    // ---- block reduction (pen, mse) ----
    float pen = (a0 + a1) + (a2 + a3);
#pragma unroll
    for (int o = 16; o > 0; o >>= 1) {
        pen += __shfl_xor_sync(0xffffffffu, pen, o);
        mse += __shfl_xor_sync(0xffffffffu, mse, o);
    }
    if (lane == 0) { smP[w] = pen; smM[w] = mse; }
    __syncthreads();
    if (tid == 0) {
        float ps = 0.f, ms = 0.f;
#pragma unroll
        for (int x = 0; x < TPB / 32; x++) { ps += smP[x]; ms += smM[x]; }
        g_pen[b] = ps;
        g_mse[b] = ms;
        __threadfence();
        int ticket = atomicAdd(&g_cnt, 1);
        lastFlag = (ticket == NCELL - 1);
    }
    __syncthreads();

    // ---- last block: deterministic fp64 final reduction ----
    if (lastFlag && w == 0) {
        double pd = 0.0, md = 0.0;
#pragma unroll
        for (int x = 0; x < 4; x++) {
            int idx = lane + x * 32;
            if (idx < NCELL) {
                pd += (double)__ldcg(&g_pen[idx]);
                md += (double)__ldcg(&g_mse[idx]);
            }
        }
#pragma unroll
        for (int o = 16; o > 0; o >>= 1) {
            pd += __shfl_xor_sync(0xffffffffu, pd, o);
            md += __shfl_xor_sync(0xffffffffu, md, o);
        }
        if (lane == 0) {
            out[0] = (float)(md * (1.0 / (double)(NPTS * 2)) + pd);
            g_cnt  = 0;
        }
    }
}

extern "C" void kernel_launch(void* const* d_in, const int* in_sizes, int n_in,
                              void* d_out, int out_size) {
    const float2* pred = (const float2*)d_in[0];
    const float2* targ = (const float2*)d_in[1];
    k_all<<<NCELL, TPB>>>(pred, targ, (float*)d_out);
}